// round 1
// baseline (speedup 1.0000x reference)
#include <cuda_runtime.h>

// Problem constants
#define B_    4
#define NQ    2048
#define NKV   2048
#define CQ    1024
#define CKV   768
#define NH    16
#define HD    64
#define SCALE 0.125f        // HD^-0.5
#define CLAMP_V 1.0e4f

// Scratch (allocation-free: __device__ globals)
__device__ float g_q[B_ * NQ * CQ];
__device__ float g_k[B_ * NKV * CQ];
__device__ float g_v[B_ * NKV * CQ];
__device__ float g_x[B_ * NQ * CQ];

// ---------------------------------------------------------------------------
// SGEMM with bias: C[M,N] = A[M,K] @ W[K,N] + bias[N]
// BM=BN=128, BK=16, 256 threads, 8x8 per thread.
// Requires M%128==0, N%128==0, K%16==0 (all shapes here satisfy this).
// ---------------------------------------------------------------------------
__global__ __launch_bounds__(256) void sgemm_bias(
    const float* __restrict__ A, const float* __restrict__ W,
    const float* __restrict__ bias, float* __restrict__ C,
    int M, int K, int N)
{
    __shared__ float As[16][128];   // transposed A tile
    __shared__ float Ws[16][128];

    const int tid = threadIdx.x;
    const int tx  = tid & 15;
    const int ty  = tid >> 4;
    const int m0  = blockIdx.y * 128;
    const int n0  = blockIdx.x * 128;

    // load-index precompute
    const int ar  = tid >> 2;          // 0..63   (A row within tile)
    const int ak  = (tid & 3) * 4;     // 0,4,8,12 (A k-col within tile)
    const int wr  = tid >> 5;          // 0..7    (W k-row within tile)
    const int wc  = (tid & 31) * 4;    // 0..124  (W n-col within tile)

    float acc[8][8];
#pragma unroll
    for (int i = 0; i < 8; i++)
#pragma unroll
        for (int j = 0; j < 8; j++) acc[i][j] = 0.0f;

    for (int k0 = 0; k0 < K; k0 += 16) {
        // stage A (transposed) -- two float4 per thread
        float4 a0 = *(const float4*)&A[(size_t)(m0 + ar)      * K + k0 + ak];
        float4 a1 = *(const float4*)&A[(size_t)(m0 + ar + 64) * K + k0 + ak];
        As[ak + 0][ar]      = a0.x; As[ak + 1][ar]      = a0.y;
        As[ak + 2][ar]      = a0.z; As[ak + 3][ar]      = a0.w;
        As[ak + 0][ar + 64] = a1.x; As[ak + 1][ar + 64] = a1.y;
        As[ak + 2][ar + 64] = a1.z; As[ak + 3][ar + 64] = a1.w;
        // stage W -- two float4 per thread
        float4 w0 = *(const float4*)&W[(size_t)(k0 + wr)     * N + n0 + wc];
        float4 w1 = *(const float4*)&W[(size_t)(k0 + wr + 8) * N + n0 + wc];
        *(float4*)&Ws[wr][wc]     = w0;
        *(float4*)&Ws[wr + 8][wc] = w1;
        __syncthreads();

#pragma unroll
        for (int k = 0; k < 16; k++) {
            float4 af0 = *(const float4*)&As[k][ty * 4];
            float4 af1 = *(const float4*)&As[k][64 + ty * 4];
            float4 bf0 = *(const float4*)&Ws[k][tx * 4];
            float4 bf1 = *(const float4*)&Ws[k][64 + tx * 4];
            float a[8] = {af0.x, af0.y, af0.z, af0.w, af1.x, af1.y, af1.z, af1.w};
            float b[8] = {bf0.x, bf0.y, bf0.z, bf0.w, bf1.x, bf1.y, bf1.z, bf1.w};
#pragma unroll
            for (int i = 0; i < 8; i++)
#pragma unroll
                for (int j = 0; j < 8; j++)
                    acc[i][j] = fmaf(a[i], b[j], acc[i][j]);
        }
        __syncthreads();
    }

    // epilogue with bias
#pragma unroll
    for (int ii = 0; ii < 2; ii++)
#pragma unroll
        for (int i = 0; i < 4; i++) {
            int row = m0 + ii * 64 + ty * 4 + i;
#pragma unroll
            for (int jj = 0; jj < 2; jj++) {
                int col = n0 + jj * 64 + tx * 4;
                float4 bv = *(const float4*)&bias[col];
                float4 o;
                o.x = acc[ii * 4 + i][jj * 4 + 0] + bv.x;
                o.y = acc[ii * 4 + i][jj * 4 + 1] + bv.y;
                o.z = acc[ii * 4 + i][jj * 4 + 2] + bv.z;
                o.w = acc[ii * 4 + i][jj * 4 + 3] + bv.w;
                *(float4*)&C[(size_t)row * N + col] = o;
            }
        }
}

// ---------------------------------------------------------------------------
// Flash attention over projected Q/K/V laid out as [B*N, H*D] row-major.
// grid = (NQ/64, NH, B_), block = 256 threads.
// Per block: 64 q-rows of one (b,h); loop over kv in chunks of 64.
// Fragments: thread (ty,tx) owns q-rows {ty+16i}, kv/d-cols {tx+16j}.
// ---------------------------------------------------------------------------
#define LDP 68   // smem row stride (floats): 16B-aligned, low-conflict

__device__ __forceinline__ float redmax16(float v) {
    v = fmaxf(v, __shfl_xor_sync(0xffffffffu, v, 1));
    v = fmaxf(v, __shfl_xor_sync(0xffffffffu, v, 2));
    v = fmaxf(v, __shfl_xor_sync(0xffffffffu, v, 4));
    v = fmaxf(v, __shfl_xor_sync(0xffffffffu, v, 8));
    return v;
}
__device__ __forceinline__ float redsum16(float v) {
    v += __shfl_xor_sync(0xffffffffu, v, 1);
    v += __shfl_xor_sync(0xffffffffu, v, 2);
    v += __shfl_xor_sync(0xffffffffu, v, 4);
    v += __shfl_xor_sync(0xffffffffu, v, 8);
    return v;
}

__global__ __launch_bounds__(256) void flash_attn(
    const float* __restrict__ Qp, const float* __restrict__ Kp,
    const float* __restrict__ Vp, float* __restrict__ X)
{
    extern __shared__ float sm[];
    float* Qs = sm;                 // [64][LDP]
    float* Ks = Qs + 64 * LDP;
    float* Vs = Ks + 64 * LDP;
    float* Ps = Vs + 64 * LDP;

    const int tid = threadIdx.x;
    const int tx  = tid & 15;
    const int ty  = tid >> 4;
    const int qt  = blockIdx.x;
    const int h   = blockIdx.y;
    const int b   = blockIdx.z;
    const int hc  = h * HD;
    const int qrow0 = b * NQ + qt * 64;   // global row into [B*NQ, CQ]
    const int kvrow0 = b * NKV;

    // load Q tile (scale folded in)
#pragma unroll
    for (int i = 0; i < 4; i++) {
        int idx = tid + i * 256;          // 0..1023
        int r = idx >> 4, c = (idx & 15) * 4;
        float4 v = *(const float4*)&Qp[(size_t)(qrow0 + r) * CQ + hc + c];
        Qs[r * LDP + c + 0] = v.x * SCALE;
        Qs[r * LDP + c + 1] = v.y * SCALE;
        Qs[r * LDP + c + 2] = v.z * SCALE;
        Qs[r * LDP + c + 3] = v.w * SCALE;
    }

    float m_i[4], l_i[4], o[4][4];
#pragma unroll
    for (int i = 0; i < 4; i++) {
        m_i[i] = -1e30f; l_i[i] = 0.0f;
#pragma unroll
        for (int j = 0; j < 4; j++) o[i][j] = 0.0f;
    }

    for (int kt = 0; kt < NKV; kt += 64) {
        // stage K and V chunks
#pragma unroll
        for (int i = 0; i < 4; i++) {
            int idx = tid + i * 256;
            int r = idx >> 4, c = (idx & 15) * 4;
            size_t g = (size_t)(kvrow0 + kt + r) * CQ + hc + c;
            float4 kv4 = *(const float4*)&Kp[g];
            Ks[r * LDP + c + 0] = kv4.x; Ks[r * LDP + c + 1] = kv4.y;
            Ks[r * LDP + c + 2] = kv4.z; Ks[r * LDP + c + 3] = kv4.w;
            float4 vv4 = *(const float4*)&Vp[g];
            Vs[r * LDP + c + 0] = vv4.x; Vs[r * LDP + c + 1] = vv4.y;
            Vs[r * LDP + c + 2] = vv4.z; Vs[r * LDP + c + 3] = vv4.w;
        }
        __syncthreads();   // K/V (and Q on first iter) visible

        // S = (Q*scale) @ K^T for this 64x64 tile
        float s[4][4];
#pragma unroll
        for (int i = 0; i < 4; i++)
#pragma unroll
            for (int j = 0; j < 4; j++) s[i][j] = 0.0f;

#pragma unroll
        for (int d = 0; d < 64; d += 4) {
            float aq[4][4], ak2[4][4];
#pragma unroll
            for (int i = 0; i < 4; i++) {
                float4 t = *(const float4*)&Qs[(ty + 16 * i) * LDP + d];
                aq[i][0] = t.x; aq[i][1] = t.y; aq[i][2] = t.z; aq[i][3] = t.w;
            }
#pragma unroll
            for (int j = 0; j < 4; j++) {
                float4 t = *(const float4*)&Ks[(tx + 16 * j) * LDP + d];
                ak2[j][0] = t.x; ak2[j][1] = t.y; ak2[j][2] = t.z; ak2[j][3] = t.w;
            }
#pragma unroll
            for (int q = 0; q < 4; q++)
#pragma unroll
                for (int i = 0; i < 4; i++)
#pragma unroll
                    for (int j = 0; j < 4; j++)
                        s[i][j] = fmaf(aq[i][q], ak2[j][q], s[i][j]);
        }

        // clamp + online softmax update
        float m_new[4], rs[4], alpha[4];
#pragma unroll
        for (int i = 0; i < 4; i++) {
            float mx = -1e30f;
#pragma unroll
            for (int j = 0; j < 4; j++) {
                s[i][j] = fminf(fmaxf(s[i][j], -CLAMP_V), CLAMP_V);
                mx = fmaxf(mx, s[i][j]);
            }
            mx = redmax16(mx);
            m_new[i] = fmaxf(m_i[i], mx);
            float r = 0.0f;
#pragma unroll
            for (int j = 0; j < 4; j++) {
                s[i][j] = __expf(s[i][j] - m_new[i]);   // now holds P
                r += s[i][j];
            }
            rs[i] = redsum16(r);
            alpha[i] = __expf(m_i[i] - m_new[i]);
            l_i[i] = l_i[i] * alpha[i] + rs[i];
            m_i[i] = m_new[i];
#pragma unroll
            for (int j = 0; j < 4; j++) o[i][j] *= alpha[i];
        }

        // write P to smem
#pragma unroll
        for (int i = 0; i < 4; i++)
#pragma unroll
            for (int j = 0; j < 4; j++)
                Ps[(ty + 16 * i) * LDP + tx + 16 * j] = s[i][j];
        __syncthreads();   // P visible

        // O += P @ V
#pragma unroll
        for (int kk = 0; kk < 64; kk += 4) {
            float pl[4][4];
#pragma unroll
            for (int i = 0; i < 4; i++) {
                float4 t = *(const float4*)&Ps[(ty + 16 * i) * LDP + kk];
                pl[i][0] = t.x; pl[i][1] = t.y; pl[i][2] = t.z; pl[i][3] = t.w;
            }
#pragma unroll
            for (int q = 0; q < 4; q++) {
                float vv[4];
#pragma unroll
                for (int j = 0; j < 4; j++)
                    vv[j] = Vs[(kk + q) * LDP + tx + 16 * j];
#pragma unroll
                for (int i = 0; i < 4; i++)
#pragma unroll
                    for (int j = 0; j < 4; j++)
                        o[i][j] = fmaf(pl[i][q], vv[j], o[i][j]);
            }
        }
        __syncthreads();   // done with Ks/Vs/Ps before next chunk overwrites
    }

    // normalize and write out as [B*NQ, H*D]
#pragma unroll
    for (int i = 0; i < 4; i++) {
        float inv_l = 1.0f / l_i[i];
#pragma unroll
        for (int j = 0; j < 4; j++)
            X[(size_t)(qrow0 + ty + 16 * i) * CQ + hc + tx + 16 * j] = o[i][j] * inv_l;
    }
}

// ---------------------------------------------------------------------------
// launch
// ---------------------------------------------------------------------------
extern "C" void kernel_launch(void* const* d_in, const int* in_sizes, int n_in,
                              void* d_out, int out_size)
{
    const float* query = (const float*)d_in[0];
    const float* kv    = (const float*)d_in[1];
    const float* Wq    = (const float*)d_in[2];
    const float* bq    = (const float*)d_in[3];
    const float* Wk    = (const float*)d_in[4];
    const float* bk    = (const float*)d_in[5];
    const float* Wv    = (const float*)d_in[6];
    const float* bv    = (const float*)d_in[7];
    const float* Wo    = (const float*)d_in[8];
    const float* bo    = (const float*)d_in[9];
    float* out = (float*)d_out;

    float *qp, *kp, *vp, *xp;
    cudaGetSymbolAddress((void**)&qp, g_q);
    cudaGetSymbolAddress((void**)&kp, g_k);
    cudaGetSymbolAddress((void**)&vp, g_v);
    cudaGetSymbolAddress((void**)&xp, g_x);

    const int M = B_ * NQ;     // 8192
    dim3 blk(256);
    dim3 gg(CQ / 128, M / 128);

    sgemm_bias<<<gg, blk>>>(query, Wq, bq, qp, M, CQ, CQ);
    sgemm_bias<<<gg, blk>>>(kv,    Wk, bk, kp, M, CKV, CQ);
    sgemm_bias<<<gg, blk>>>(kv,    Wv, bv, vp, M, CKV, CQ);

    const int flash_smem = 4 * 64 * LDP * sizeof(float);  // 69632 B
    cudaFuncSetAttribute(flash_attn, cudaFuncAttributeMaxDynamicSharedMemorySize,
                         flash_smem);
    flash_attn<<<dim3(NQ / 64, NH, B_), blk, flash_smem>>>(qp, kp, vp, xp);

    sgemm_bias<<<gg, blk>>>(xp, Wo, bo, out, M, CQ, CQ);
}

// round 3
// speedup vs baseline: 1.2216x; 1.2216x over previous
#include <cuda_runtime.h>
#include <cuda_bf16.h>
#include <cstdint>

// Problem constants
#define B_    4
#define NQ    2048
#define NKV   2048
#define CQ    1024
#define CKV   768
#define NH    16
#define HD    64
#define SCALE 0.125f        // HD^-0.5
#define CLAMP_V 1.0e4f

// Scratch (allocation-free: __device__ globals)
__device__ float g_q[B_ * NQ * CQ];
__device__ float g_k[B_ * NKV * CQ];
__device__ float g_v[B_ * NKV * CQ];
__device__ float g_x[B_ * NQ * CQ];

// Pre-transposed + hi/lo-split weights, [N][K] K-major bf16
__device__ __nv_bfloat16 g_wqh[CQ * CQ],  g_wql[CQ * CQ];
__device__ __nv_bfloat16 g_wkh[CQ * CKV], g_wkl[CQ * CKV];
__device__ __nv_bfloat16 g_wvh[CQ * CKV], g_wvl[CQ * CKV];
__device__ __nv_bfloat16 g_woh[CQ * CQ],  g_wol[CQ * CQ];

// ---------------------------------------------------------------------------
// helpers
// ---------------------------------------------------------------------------
__device__ __forceinline__ uint32_t smem_u32(const void* p) {
    uint32_t a;
    asm("{ .reg .u64 t; cvta.to.shared.u64 t, %1; cvt.u32.u64 %0, t; }"
        : "=r"(a) : "l"(p));
    return a;
}

__device__ __forceinline__ void ldm_x4(uint32_t* r, uint32_t addr) {
    asm volatile("ldmatrix.sync.aligned.m8n8.x4.shared.b16 {%0,%1,%2,%3}, [%4];"
        : "=r"(r[0]), "=r"(r[1]), "=r"(r[2]), "=r"(r[3]) : "r"(addr));
}

__device__ __forceinline__ void mma_bf16(float* c, const uint32_t* a,
                                         uint32_t b0, uint32_t b1) {
    asm volatile(
        "mma.sync.aligned.m16n8k16.row.col.f32.bf16.bf16.f32 "
        "{%0,%1,%2,%3}, {%4,%5,%6,%7}, {%8,%9}, {%0,%1,%2,%3};"
        : "+f"(c[0]), "+f"(c[1]), "+f"(c[2]), "+f"(c[3])
        : "r"(a[0]), "r"(a[1]), "r"(a[2]), "r"(a[3]), "r"(b0), "r"(b1));
}

#define SWZ(o) ((o) ^ (((o) >> 3) & 0x70))

// bf16 hi/lo split
__device__ __forceinline__ void bsplit(float x, uint32_t& hi, uint32_t& lo) {
    __nv_bfloat16 h = __float2bfloat16(x);
    float r = x - __bfloat162float(h);
    __nv_bfloat16 l = __float2bfloat16(r);
    hi = (uint32_t)__bfloat16_as_ushort(h);
    lo = (uint32_t)__bfloat16_as_ushort(l);
}

// ---------------------------------------------------------------------------
// Weight pre-pass: W[K,N] fp32 -> Thi/Tlo[N,K] bf16 (transposed + split)
// block (32,8), grid (N/32, K/32)
// ---------------------------------------------------------------------------
__global__ void wsplit_t(const float* __restrict__ W,
                         __nv_bfloat16* __restrict__ Thi,
                         __nv_bfloat16* __restrict__ Tlo, int K, int N)
{
    __shared__ float t[32][33];
    const int n0 = blockIdx.x * 32, k0 = blockIdx.y * 32;
    const int tx = threadIdx.x, ty = threadIdx.y;
#pragma unroll
    for (int e = 0; e < 4; e++)
        t[ty + 8 * e][tx] = W[(size_t)(k0 + ty + 8 * e) * N + n0 + tx];
    __syncthreads();
#pragma unroll
    for (int e = 0; e < 4; e++) {
        float x = t[tx][ty + 8 * e];
        __nv_bfloat16 h = __float2bfloat16(x);
        __nv_bfloat16 l = __float2bfloat16(x - __bfloat162float(h));
        size_t o = (size_t)(n0 + ty + 8 * e) * K + k0 + tx;
        Thi[o] = h;
        Tlo[o] = l;
    }
}

// ---------------------------------------------------------------------------
// mma.sync split-bf16 GEMM: C[M,N] = A[M,K] @ B^T + bias, B = [N,K] bf16 hi/lo
// CTA tile 128x128, K-chunk 64, 256 threads (8 warps = 4m x 2n, warp 32x64).
// Requires M%128==0, N%128==0, K%64==0.
// ---------------------------------------------------------------------------
#define OFF_BIAS 0
#define OFF_AHI  1024
#define OFF_ALO  (OFF_AHI + 16384)
#define OFF_BHI  (OFF_ALO + 16384)
#define OFF_BLO  (OFF_BHI + 16384)
#define SMEM_GEMM (OFF_BLO + 16384)   // 66560 B

__global__ __launch_bounds__(256)
void gemm_tc(const float* __restrict__ A,
             const __nv_bfloat16* __restrict__ Bhi,
             const __nv_bfloat16* __restrict__ Blo,
             const float* __restrict__ bias,
             float* __restrict__ C, int M, int K, int N)
{
    extern __shared__ char sm[];
    const uint32_t sb = smem_u32(sm);
    const int tid  = threadIdx.x;
    const int wid  = tid >> 5, lane = tid & 31;
    const int n0   = blockIdx.x * 128, m0 = blockIdx.y * 128;
    const int wm   = wid & 3;      // m block (32 rows)
    const int wn   = wid >> 2;     // n block (64 cols)

    if (tid < 128) ((float*)(sm + OFF_BIAS))[tid] = bias[n0 + tid];

    float acc[2][8][4];
#pragma unroll
    for (int i = 0; i < 2; i++)
#pragma unroll
        for (int j = 0; j < 8; j++)
#pragma unroll
            for (int q = 0; q < 4; q++) acc[i][j][q] = 0.0f;

    // ldmatrix lane addressing (bf16-element indices; *2 for bytes)
    const int arow = wm * 32 + (lane & 15);
    const int acol = (lane >> 4) << 3;                       // 0 / 8
    const int brow = wn * 64 + ((lane >> 4) << 3) + (lane & 7);
    const int bcol = ((lane >> 3) & 1) << 3;                 // 0 / 8

    const int nchunks = K >> 6;
    for (int c = 0; c < nchunks; c++) {
        const int k0 = c << 6;
        // ---- stage A (fp32 -> bf16 hi/lo, SW128) ----
#pragma unroll
        for (int i = 0; i < 8; i++) {
            int flat = tid + i * 256;          // 0..2047 float4s
            int row = flat >> 4, cg = (flat & 15) * 4;
            float4 a = *(const float4*)&A[(size_t)(m0 + row) * K + k0 + cg];
            uint32_t h0, l0, h1, l1, h2, l2, h3, l3;
            bsplit(a.x, h0, l0); bsplit(a.y, h1, l1);
            bsplit(a.z, h2, l2); bsplit(a.w, h3, l3);
            unsigned long long hv = (unsigned long long)(h0 | (h1 << 16)) |
                                    ((unsigned long long)(h2 | (h3 << 16)) << 32);
            unsigned long long lv = (unsigned long long)(l0 | (l1 << 16)) |
                                    ((unsigned long long)(l2 | (l3 << 16)) << 32);
            int sw = SWZ(row * 128 + cg * 2);
            *(unsigned long long*)(sm + OFF_AHI + sw) = hv;
            *(unsigned long long*)(sm + OFF_ALO + sw) = lv;
        }
        // ---- stage B (pre-split bf16, straight copy, SW128) ----
#pragma unroll
        for (int i = 0; i < 8; i++) {
            int flat = tid + i * 256;          // 0..2047 u64s
            int row = flat >> 4, seg = flat & 15;
            const unsigned long long* ph =
                (const unsigned long long*)(Bhi + (size_t)(n0 + row) * K + k0);
            const unsigned long long* pl =
                (const unsigned long long*)(Blo + (size_t)(n0 + row) * K + k0);
            int sw = SWZ(row * 128 + seg * 8);
            *(unsigned long long*)(sm + OFF_BHI + sw) = ph[seg];
            *(unsigned long long*)(sm + OFF_BLO + sw) = pl[seg];
        }
        __syncthreads();

        // ---- compute: 4 k-steps of 16 ----
#pragma unroll
        for (int ks = 0; ks < 4; ks++) {
            uint32_t ah[2][4], al[2][4];
#pragma unroll
            for (int mi = 0; mi < 2; mi++) {
                uint32_t off = SWZ((arow + mi * 16) * 128 + (ks * 16 + acol) * 2);
                ldm_x4(ah[mi], sb + OFF_AHI + off);
                ldm_x4(al[mi], sb + OFF_ALO + off);
            }
#pragma unroll
            for (int nb = 0; nb < 4; nb++) {
                uint32_t off = SWZ((brow + nb * 16) * 128 + (ks * 16 + bcol) * 2);
                uint32_t bh[4], bl[4];
                ldm_x4(bh, sb + OFF_BHI + off);
                ldm_x4(bl, sb + OFF_BLO + off);
#pragma unroll
                for (int h = 0; h < 2; h++)
#pragma unroll
                    for (int mi = 0; mi < 2; mi++) {
                        float* cc = acc[mi][nb * 2 + h];
                        mma_bf16(cc, ah[mi], bh[2 * h], bh[2 * h + 1]);
                        mma_bf16(cc, ah[mi], bl[2 * h], bl[2 * h + 1]);
                        mma_bf16(cc, al[mi], bh[2 * h], bh[2 * h + 1]);
                    }
            }
        }
        __syncthreads();
    }

    // ---- epilogue: bias add + store ----
    const float* bsm = (const float*)(sm + OFF_BIAS);
    const int qr = lane >> 2;            // 0..7
    const int qc = (lane & 3) * 2;       // 0,2,4,6
#pragma unroll
    for (int mi = 0; mi < 2; mi++) {
        const int r0 = m0 + wm * 32 + mi * 16 + qr;
#pragma unroll
        for (int j = 0; j < 8; j++) {
            const int cb = wn * 64 + j * 8 + qc;       // col within CTA tile
            const int col = n0 + cb;
            float2 o0, o1;
            o0.x = acc[mi][j][0] + bsm[cb];
            o0.y = acc[mi][j][1] + bsm[cb + 1];
            o1.x = acc[mi][j][2] + bsm[cb];
            o1.y = acc[mi][j][3] + bsm[cb + 1];
            *(float2*)&C[(size_t)r0 * N + col]       = o0;
            *(float2*)&C[(size_t)(r0 + 8) * N + col] = o1;
        }
    }
}

// ---------------------------------------------------------------------------
// Flash attention (unchanged, verified) over [B*N, H*D] fp32
// ---------------------------------------------------------------------------
#define LDP 68

__device__ __forceinline__ float redmax16(float v) {
    v = fmaxf(v, __shfl_xor_sync(0xffffffffu, v, 1));
    v = fmaxf(v, __shfl_xor_sync(0xffffffffu, v, 2));
    v = fmaxf(v, __shfl_xor_sync(0xffffffffu, v, 4));
    v = fmaxf(v, __shfl_xor_sync(0xffffffffu, v, 8));
    return v;
}
__device__ __forceinline__ float redsum16(float v) {
    v += __shfl_xor_sync(0xffffffffu, v, 1);
    v += __shfl_xor_sync(0xffffffffu, v, 2);
    v += __shfl_xor_sync(0xffffffffu, v, 4);
    v += __shfl_xor_sync(0xffffffffu, v, 8);
    return v;
}

__global__ __launch_bounds__(256) void flash_attn(
    const float* __restrict__ Qp, const float* __restrict__ Kp,
    const float* __restrict__ Vp, float* __restrict__ X)
{
    extern __shared__ float smf[];
    float* Qs = smf;
    float* Ks = Qs + 64 * LDP;
    float* Vs = Ks + 64 * LDP;
    float* Ps = Vs + 64 * LDP;

    const int tid = threadIdx.x;
    const int tx  = tid & 15;
    const int ty  = tid >> 4;
    const int qt  = blockIdx.x;
    const int h   = blockIdx.y;
    const int b   = blockIdx.z;
    const int hc  = h * HD;
    const int qrow0 = b * NQ + qt * 64;
    const int kvrow0 = b * NKV;

#pragma unroll
    for (int i = 0; i < 4; i++) {
        int idx = tid + i * 256;
        int r = idx >> 4, c = (idx & 15) * 4;
        float4 v = *(const float4*)&Qp[(size_t)(qrow0 + r) * CQ + hc + c];
        Qs[r * LDP + c + 0] = v.x * SCALE;
        Qs[r * LDP + c + 1] = v.y * SCALE;
        Qs[r * LDP + c + 2] = v.z * SCALE;
        Qs[r * LDP + c + 3] = v.w * SCALE;
    }

    float m_i[4], l_i[4], o[4][4];
#pragma unroll
    for (int i = 0; i < 4; i++) {
        m_i[i] = -1e30f; l_i[i] = 0.0f;
#pragma unroll
        for (int j = 0; j < 4; j++) o[i][j] = 0.0f;
    }

    for (int kt = 0; kt < NKV; kt += 64) {
#pragma unroll
        for (int i = 0; i < 4; i++) {
            int idx = tid + i * 256;
            int r = idx >> 4, c = (idx & 15) * 4;
            size_t g = (size_t)(kvrow0 + kt + r) * CQ + hc + c;
            float4 kv4 = *(const float4*)&Kp[g];
            Ks[r * LDP + c + 0] = kv4.x; Ks[r * LDP + c + 1] = kv4.y;
            Ks[r * LDP + c + 2] = kv4.z; Ks[r * LDP + c + 3] = kv4.w;
            float4 vv4 = *(const float4*)&Vp[g];
            Vs[r * LDP + c + 0] = vv4.x; Vs[r * LDP + c + 1] = vv4.y;
            Vs[r * LDP + c + 2] = vv4.z; Vs[r * LDP + c + 3] = vv4.w;
        }
        __syncthreads();

        float s[4][4];
#pragma unroll
        for (int i = 0; i < 4; i++)
#pragma unroll
            for (int j = 0; j < 4; j++) s[i][j] = 0.0f;

#pragma unroll
        for (int d = 0; d < 64; d += 4) {
            float aq[4][4], ak2[4][4];
#pragma unroll
            for (int i = 0; i < 4; i++) {
                float4 t = *(const float4*)&Qs[(ty + 16 * i) * LDP + d];
                aq[i][0] = t.x; aq[i][1] = t.y; aq[i][2] = t.z; aq[i][3] = t.w;
            }
#pragma unroll
            for (int j = 0; j < 4; j++) {
                float4 t = *(const float4*)&Ks[(tx + 16 * j) * LDP + d];
                ak2[j][0] = t.x; ak2[j][1] = t.y; ak2[j][2] = t.z; ak2[j][3] = t.w;
            }
#pragma unroll
            for (int q = 0; q < 4; q++)
#pragma unroll
                for (int i = 0; i < 4; i++)
#pragma unroll
                    for (int j = 0; j < 4; j++)
                        s[i][j] = fmaf(aq[i][q], ak2[j][q], s[i][j]);
        }

        float m_new[4], rs[4], alpha[4];
#pragma unroll
        for (int i = 0; i < 4; i++) {
            float mx = -1e30f;
#pragma unroll
            for (int j = 0; j < 4; j++) {
                s[i][j] = fminf(fmaxf(s[i][j], -CLAMP_V), CLAMP_V);
                mx = fmaxf(mx, s[i][j]);
            }
            mx = redmax16(mx);
            m_new[i] = fmaxf(m_i[i], mx);
            float r = 0.0f;
#pragma unroll
            for (int j = 0; j < 4; j++) {
                s[i][j] = __expf(s[i][j] - m_new[i]);
                r += s[i][j];
            }
            rs[i] = redsum16(r);
            alpha[i] = __expf(m_i[i] - m_new[i]);
            l_i[i] = l_i[i] * alpha[i] + rs[i];
            m_i[i] = m_new[i];
#pragma unroll
            for (int j = 0; j < 4; j++) o[i][j] *= alpha[i];
        }

#pragma unroll
        for (int i = 0; i < 4; i++)
#pragma unroll
            for (int j = 0; j < 4; j++)
                Ps[(ty + 16 * i) * LDP + tx + 16 * j] = s[i][j];
        __syncthreads();

#pragma unroll
        for (int kk = 0; kk < 64; kk += 4) {
            float pl[4][4];
#pragma unroll
            for (int i = 0; i < 4; i++) {
                float4 t = *(const float4*)&Ps[(ty + 16 * i) * LDP + kk];
                pl[i][0] = t.x; pl[i][1] = t.y; pl[i][2] = t.z; pl[i][3] = t.w;
            }
#pragma unroll
            for (int q = 0; q < 4; q++) {
                float vv[4];
#pragma unroll
                for (int j = 0; j < 4; j++)
                    vv[j] = Vs[(kk + q) * LDP + tx + 16 * j];
#pragma unroll
                for (int i = 0; i < 4; i++)
#pragma unroll
                    for (int j = 0; j < 4; j++)
                        o[i][j] = fmaf(pl[i][q], vv[j], o[i][j]);
            }
        }
        __syncthreads();
    }

#pragma unroll
    for (int i = 0; i < 4; i++) {
        float inv_l = 1.0f / l_i[i];
#pragma unroll
        for (int j = 0; j < 4; j++)
            X[(size_t)(qrow0 + ty + 16 * i) * CQ + hc + tx + 16 * j] = o[i][j] * inv_l;
    }
}

// ---------------------------------------------------------------------------
// launch
// ---------------------------------------------------------------------------
extern "C" void kernel_launch(void* const* d_in, const int* in_sizes, int n_in,
                              void* d_out, int out_size)
{
    const float* query = (const float*)d_in[0];
    const float* kv    = (const float*)d_in[1];
    const float* Wq    = (const float*)d_in[2];
    const float* bq    = (const float*)d_in[3];
    const float* Wk    = (const float*)d_in[4];
    const float* bk    = (const float*)d_in[5];
    const float* Wv    = (const float*)d_in[6];
    const float* bv    = (const float*)d_in[7];
    const float* Wo    = (const float*)d_in[8];
    const float* bo    = (const float*)d_in[9];
    float* out = (float*)d_out;

    float *qp, *kp, *vp, *xp;
    cudaGetSymbolAddress((void**)&qp, g_q);
    cudaGetSymbolAddress((void**)&kp, g_k);
    cudaGetSymbolAddress((void**)&vp, g_v);
    cudaGetSymbolAddress((void**)&xp, g_x);

    __nv_bfloat16 *wqh, *wql, *wkh, *wkl, *wvh, *wvl, *woh, *wol;
    cudaGetSymbolAddress((void**)&wqh, g_wqh); cudaGetSymbolAddress((void**)&wql, g_wql);
    cudaGetSymbolAddress((void**)&wkh, g_wkh); cudaGetSymbolAddress((void**)&wkl, g_wkl);
    cudaGetSymbolAddress((void**)&wvh, g_wvh); cudaGetSymbolAddress((void**)&wvl, g_wvl);
    cudaGetSymbolAddress((void**)&woh, g_woh); cudaGetSymbolAddress((void**)&wol, g_wol);

    // weight transpose + split
    dim3 tb(32, 8);
    wsplit_t<<<dim3(CQ / 32, CQ / 32),  tb>>>(Wq, wqh, wql, CQ,  CQ);
    wsplit_t<<<dim3(CQ / 32, CKV / 32), tb>>>(Wk, wkh, wkl, CKV, CQ);
    wsplit_t<<<dim3(CQ / 32, CKV / 32), tb>>>(Wv, wvh, wvl, CKV, CQ);
    wsplit_t<<<dim3(CQ / 32, CQ / 32),  tb>>>(Wo, woh, wol, CQ,  CQ);

    const int M = B_ * NQ;   // 8192
    cudaFuncSetAttribute(gemm_tc, cudaFuncAttributeMaxDynamicSharedMemorySize,
                         SMEM_GEMM);
    dim3 gg(CQ / 128, M / 128);   // (8, 64)

    gemm_tc<<<gg, 256, SMEM_GEMM>>>(query, wqh, wql, bq, qp, M, CQ,  CQ);
    gemm_tc<<<gg, 256, SMEM_GEMM>>>(kv,    wkh, wkl, bk, kp, M, CKV, CQ);
    gemm_tc<<<gg, 256, SMEM_GEMM>>>(kv,    wvh, wvl, bv, vp, M, CKV, CQ);

    const int flash_smem = 4 * 64 * LDP * sizeof(float);
    cudaFuncSetAttribute(flash_attn, cudaFuncAttributeMaxDynamicSharedMemorySize,
                         flash_smem);
    flash_attn<<<dim3(NQ / 64, NH, B_), 256, flash_smem>>>(qp, kp, vp, xp);

    gemm_tc<<<gg, 256, SMEM_GEMM>>>(xp, woh, wol, bo, out, M, CQ, CQ);
}

// round 5
// speedup vs baseline: 1.5203x; 1.2445x over previous
#include <cuda_runtime.h>
#include <cuda_bf16.h>
#include <cstdint>

// Problem constants
#define B_    4
#define NQ    2048
#define NKV   2048
#define CQ    1024
#define CKV   768
#define NH    16
#define HD    64
#define SCALE 0.125f        // HD^-0.5
#define CLAMP_V 1.0e4f

// Scratch (allocation-free: __device__ globals). All bf16 hi/lo pairs.
__device__ __nv_bfloat16 g_qh[B_ * NQ * CQ],  g_ql[B_ * NQ * CQ];
__device__ __nv_bfloat16 g_kh[B_ * NKV * CQ], g_kl[B_ * NKV * CQ];
__device__ __nv_bfloat16 g_vth[B_ * CQ * NKV], g_vtl[B_ * CQ * NKV]; // [b*CQ+col][kv]
__device__ __nv_bfloat16 g_xh[B_ * NQ * CQ],  g_xl[B_ * NQ * CQ];

// Pre-transposed + hi/lo-split weights, [N][K] K-major bf16
__device__ __nv_bfloat16 g_wqh[CQ * CQ],  g_wql[CQ * CQ];
__device__ __nv_bfloat16 g_wkh[CQ * CKV], g_wkl[CQ * CKV];
__device__ __nv_bfloat16 g_wvh[CQ * CKV], g_wvl[CQ * CKV];
__device__ __nv_bfloat16 g_woh[CQ * CQ],  g_wol[CQ * CQ];

// ---------------------------------------------------------------------------
// helpers
// ---------------------------------------------------------------------------
__device__ __forceinline__ uint32_t smem_u32(const void* p) {
    uint32_t a;
    asm("{ .reg .u64 t; cvta.to.shared.u64 t, %1; cvt.u32.u64 %0, t; }"
        : "=r"(a) : "l"(p));
    return a;
}
__device__ __forceinline__ void ldm_x4(uint32_t* r, uint32_t addr) {
    asm volatile("ldmatrix.sync.aligned.m8n8.x4.shared.b16 {%0,%1,%2,%3}, [%4];"
        : "=r"(r[0]), "=r"(r[1]), "=r"(r[2]), "=r"(r[3]) : "r"(addr));
}
__device__ __forceinline__ void mma_bf16(float* c, const uint32_t* a,
                                         uint32_t b0, uint32_t b1) {
    asm volatile(
        "mma.sync.aligned.m16n8k16.row.col.f32.bf16.bf16.f32 "
        "{%0,%1,%2,%3}, {%4,%5,%6,%7}, {%8,%9}, {%0,%1,%2,%3};"
        : "+f"(c[0]), "+f"(c[1]), "+f"(c[2]), "+f"(c[3])
        : "r"(a[0]), "r"(a[1]), "r"(a[2]), "r"(a[3]), "r"(b0), "r"(b1));
}
#define SWZ(o) ((o) ^ (((o) >> 3) & 0x70))

__device__ __forceinline__ void bsplit(float x, uint32_t& hi, uint32_t& lo) {
    __nv_bfloat16 h = __float2bfloat16(x);
    float r = x - __bfloat162float(h);
    __nv_bfloat16 l = __float2bfloat16(r);
    hi = (uint32_t)__bfloat16_as_ushort(h);
    lo = (uint32_t)__bfloat16_as_ushort(l);
}
// split two floats into packed hi pair and packed lo pair
__device__ __forceinline__ void psplit2(float a, float b,
                                        uint32_t& hp, uint32_t& lp) {
    uint32_t ha, la, hb, lb;
    bsplit(a, ha, la);
    bsplit(b, hb, lb);
    hp = ha | (hb << 16);
    lp = la | (lb << 16);
}

// ---------------------------------------------------------------------------
// Weight pre-pass: W[K,N] fp32 -> Thi/Tlo[N,K] bf16 (transposed + split)
// ---------------------------------------------------------------------------
__global__ void wsplit_t(const float* __restrict__ W,
                         __nv_bfloat16* __restrict__ Thi,
                         __nv_bfloat16* __restrict__ Tlo, int K, int N)
{
    __shared__ float t[32][33];
    const int n0 = blockIdx.x * 32, k0 = blockIdx.y * 32;
    const int tx = threadIdx.x, ty = threadIdx.y;
#pragma unroll
    for (int e = 0; e < 4; e++)
        t[ty + 8 * e][tx] = W[(size_t)(k0 + ty + 8 * e) * N + n0 + tx];
    __syncthreads();
#pragma unroll
    for (int e = 0; e < 4; e++) {
        float x = t[tx][ty + 8 * e];
        __nv_bfloat16 h = __float2bfloat16(x);
        __nv_bfloat16 l = __float2bfloat16(x - __bfloat162float(h));
        size_t o = (size_t)(n0 + ty + 8 * e) * K + k0 + tx;
        Thi[o] = h;
        Tlo[o] = l;
    }
}

// ---------------------------------------------------------------------------
// mma.sync split-bf16 GEMM, templated on input/output modes.
// AMODE 0: A fp32 [M,K], converted inline.  AMODE 1: A pre-split bf16 hi/lo.
// OMODE 0: fp32 C + bias.  OMODE 1: bf16 hi/lo C, (acc+bias)*oscale.
// OMODE 2: bf16 hi/lo transposed per-head: Vt[(b*CQ+col)*NKV + kv].
// CTA 128x128, K-chunk 64, 256 threads (8 warps = 4m x 2n).
// ---------------------------------------------------------------------------
#define OFF_BIAS 0
#define OFF_AHI  1024
#define OFF_ALO  (OFF_AHI + 16384)
#define OFF_BHI  (OFF_ALO + 16384)
#define OFF_BLO  (OFF_BHI + 16384)
#define SMEM_GEMM (OFF_BLO + 16384)   // 66560 B

template<int AMODE, int OMODE>
__global__ __launch_bounds__(256)
void gemm_tc(const float* __restrict__ Af,
             const __nv_bfloat16* __restrict__ Ah,
             const __nv_bfloat16* __restrict__ Al,
             const __nv_bfloat16* __restrict__ Bhi,
             const __nv_bfloat16* __restrict__ Blo,
             const float* __restrict__ bias,
             float* __restrict__ Cf,
             __nv_bfloat16* __restrict__ Chi,
             __nv_bfloat16* __restrict__ Clo,
             int M, int K, int N, float oscale)
{
    extern __shared__ char sm[];
    const uint32_t sb = smem_u32(sm);
    const int tid  = threadIdx.x;
    const int wid  = tid >> 5, lane = tid & 31;
    const int n0   = blockIdx.x * 128, m0 = blockIdx.y * 128;
    const int wm   = wid & 3;
    const int wn   = wid >> 2;

    if (tid < 128) ((float*)(sm + OFF_BIAS))[tid] = bias[n0 + tid];

    float acc[2][8][4];
#pragma unroll
    for (int i = 0; i < 2; i++)
#pragma unroll
        for (int j = 0; j < 8; j++)
#pragma unroll
            for (int q = 0; q < 4; q++) acc[i][j][q] = 0.0f;

    const int arow = wm * 32 + (lane & 15);
    const int acol = (lane >> 4) << 3;
    const int brow = wn * 64 + ((lane >> 4) << 3) + (lane & 7);
    const int bcol = ((lane >> 3) & 1) << 3;

    const int nchunks = K >> 6;
    for (int c = 0; c < nchunks; c++) {
        const int k0 = c << 6;
        if (AMODE == 0) {
            // stage A fp32 -> bf16 hi/lo
#pragma unroll
            for (int i = 0; i < 8; i++) {
                int flat = tid + i * 256;
                int row = flat >> 4, cg = (flat & 15) * 4;
                float4 a = *(const float4*)&Af[(size_t)(m0 + row) * K + k0 + cg];
                uint32_t h0, l0, h1, l1, h2, l2, h3, l3;
                bsplit(a.x, h0, l0); bsplit(a.y, h1, l1);
                bsplit(a.z, h2, l2); bsplit(a.w, h3, l3);
                unsigned long long hv = (unsigned long long)(h0 | (h1 << 16)) |
                                        ((unsigned long long)(h2 | (h3 << 16)) << 32);
                unsigned long long lv = (unsigned long long)(l0 | (l1 << 16)) |
                                        ((unsigned long long)(l2 | (l3 << 16)) << 32);
                int sw = SWZ(row * 128 + cg * 2);
                *(unsigned long long*)(sm + OFF_AHI + sw) = hv;
                *(unsigned long long*)(sm + OFF_ALO + sw) = lv;
            }
        } else {
            // stage pre-split A, straight copy
#pragma unroll
            for (int i = 0; i < 8; i++) {
                int flat = tid + i * 256;
                int row = flat >> 4, seg = flat & 15;
                const unsigned long long* ph =
                    (const unsigned long long*)(Ah + (size_t)(m0 + row) * K + k0);
                const unsigned long long* pl =
                    (const unsigned long long*)(Al + (size_t)(m0 + row) * K + k0);
                int sw = SWZ(row * 128 + seg * 8);
                *(unsigned long long*)(sm + OFF_AHI + sw) = ph[seg];
                *(unsigned long long*)(sm + OFF_ALO + sw) = pl[seg];
            }
        }
        // stage B (pre-split)
#pragma unroll
        for (int i = 0; i < 8; i++) {
            int flat = tid + i * 256;
            int row = flat >> 4, seg = flat & 15;
            const unsigned long long* ph =
                (const unsigned long long*)(Bhi + (size_t)(n0 + row) * K + k0);
            const unsigned long long* pl =
                (const unsigned long long*)(Blo + (size_t)(n0 + row) * K + k0);
            int sw = SWZ(row * 128 + seg * 8);
            *(unsigned long long*)(sm + OFF_BHI + sw) = ph[seg];
            *(unsigned long long*)(sm + OFF_BLO + sw) = pl[seg];
        }
        __syncthreads();

#pragma unroll
        for (int ks = 0; ks < 4; ks++) {
            uint32_t ah[2][4], al[2][4];
#pragma unroll
            for (int mi = 0; mi < 2; mi++) {
                uint32_t off = SWZ((arow + mi * 16) * 128 + (ks * 16 + acol) * 2);
                ldm_x4(ah[mi], sb + OFF_AHI + off);
                ldm_x4(al[mi], sb + OFF_ALO + off);
            }
#pragma unroll
            for (int nb = 0; nb < 4; nb++) {
                uint32_t off = SWZ((brow + nb * 16) * 128 + (ks * 16 + bcol) * 2);
                uint32_t bh[4], bl[4];
                ldm_x4(bh, sb + OFF_BHI + off);
                ldm_x4(bl, sb + OFF_BLO + off);
#pragma unroll
                for (int h = 0; h < 2; h++)
#pragma unroll
                    for (int mi = 0; mi < 2; mi++) {
                        float* cc = acc[mi][nb * 2 + h];
                        mma_bf16(cc, ah[mi], bh[2 * h], bh[2 * h + 1]);
                        mma_bf16(cc, ah[mi], bl[2 * h], bl[2 * h + 1]);
                        mma_bf16(cc, al[mi], bh[2 * h], bh[2 * h + 1]);
                    }
            }
        }
        __syncthreads();
    }

    const float* bsm = (const float*)(sm + OFF_BIAS);
    const int qr = lane >> 2;
    const int qc = (lane & 3) * 2;
#pragma unroll
    for (int mi = 0; mi < 2; mi++) {
        const int r0 = m0 + wm * 32 + mi * 16 + qr;
#pragma unroll
        for (int j = 0; j < 8; j++) {
            const int cb = wn * 64 + j * 8 + qc;
            const int col = n0 + cb;
            float v0 = acc[mi][j][0] + bsm[cb];
            float v1 = acc[mi][j][1] + bsm[cb + 1];
            float v2 = acc[mi][j][2] + bsm[cb];
            float v3 = acc[mi][j][3] + bsm[cb + 1];
            if (OMODE == 0) {
                *(float2*)&Cf[(size_t)r0 * N + col]       = make_float2(v0, v1);
                *(float2*)&Cf[(size_t)(r0 + 8) * N + col] = make_float2(v2, v3);
            } else if (OMODE == 1) {
                v0 *= oscale; v1 *= oscale; v2 *= oscale; v3 *= oscale;
                uint32_t h0, l0, h1, l1, h2, l2, h3, l3;
                bsplit(v0, h0, l0); bsplit(v1, h1, l1);
                bsplit(v2, h2, l2); bsplit(v3, h3, l3);
                *(uint32_t*)&Chi[(size_t)r0 * N + col]       = h0 | (h1 << 16);
                *(uint32_t*)&Clo[(size_t)r0 * N + col]       = l0 | (l1 << 16);
                *(uint32_t*)&Chi[(size_t)(r0 + 8) * N + col] = h2 | (h3 << 16);
                *(uint32_t*)&Clo[(size_t)(r0 + 8) * N + col] = l2 | (l3 << 16);
            } else {
                // transposed per-head: Vt[(b*CQ + col)][kv], row r0 = b*NKV + kv
                const int b  = r0 >> 11;           // NKV = 2048
                const int kv = r0 & 2047;
                uint32_t h0, l0, h1, l1, h2, l2, h3, l3;
                bsplit(v0, h0, l0); bsplit(v1, h1, l1);
                bsplit(v2, h2, l2); bsplit(v3, h3, l3);
                size_t c0 = (size_t)(b * CQ + col) * NKV + kv;
                size_t c1 = (size_t)(b * CQ + col + 1) * NKV + kv;
                Chi[c0]     = __ushort_as_bfloat16((unsigned short)h0);
                Clo[c0]     = __ushort_as_bfloat16((unsigned short)l0);
                Chi[c1]     = __ushort_as_bfloat16((unsigned short)h1);
                Clo[c1]     = __ushort_as_bfloat16((unsigned short)l1);
                Chi[c0 + 8] = __ushort_as_bfloat16((unsigned short)h2);
                Clo[c0 + 8] = __ushort_as_bfloat16((unsigned short)l2);
                Chi[c1 + 8] = __ushort_as_bfloat16((unsigned short)h3);
                Clo[c1 + 8] = __ushort_as_bfloat16((unsigned short)l3);
            }
        }
    }
}

// ---------------------------------------------------------------------------
// flash attention with mma.sync. BM=128 q rows, BN=64 kv chunk, D=64.
// grid (NQ/128, NH, B_), 256 threads (8 warps, 16 q-rows each).
// Q hi/lo and K hi/lo pre-split [B*N, CQ]; V pre-split transposed
// Vt[(b*CQ+col)][kv]. Output X as bf16 hi/lo [B*NQ, CQ].
// P is hi/lo split for P@V (3 MMAs) — required for <1e-3 accuracy.
// ---------------------------------------------------------------------------
#define F_QH 0
#define F_QL 16384
#define F_KH 32768
#define F_KL 40960
#define F_VH 49152
#define F_VL 57344
#define SMEM_FLASH 65536

__global__ __launch_bounds__(256)
void flash_mma(const __nv_bfloat16* __restrict__ Qh_g,
               const __nv_bfloat16* __restrict__ Ql_g,
               const __nv_bfloat16* __restrict__ Kh_g,
               const __nv_bfloat16* __restrict__ Kl_g,
               const __nv_bfloat16* __restrict__ Vh_g,
               const __nv_bfloat16* __restrict__ Vl_g,
               __nv_bfloat16* __restrict__ Xh_g,
               __nv_bfloat16* __restrict__ Xl_g)
{
    extern __shared__ char sm[];
    const uint32_t sb = smem_u32(sm);
    const int tid  = threadIdx.x;
    const int wid  = tid >> 5, lane = tid & 31;
    const int h    = blockIdx.y, b = blockIdx.z;
    const int hc   = h * HD;
    const int qrow0 = b * NQ + blockIdx.x * 128;

    // ---- stage Q (128 rows x 64 bf16, hi+lo) ----
#pragma unroll
    for (int i = 0; i < 4; i++) {
        int flat = tid + i * 256;            // 0..1023
        int row = flat >> 3, seg = flat & 7;
        const uint4* ph = (const uint4*)(Qh_g + (size_t)(qrow0 + row) * CQ + hc);
        const uint4* pl = (const uint4*)(Ql_g + (size_t)(qrow0 + row) * CQ + hc);
        int sw = SWZ(row * 128 + seg * 16);
        *(uint4*)(sm + F_QH + sw) = ph[seg];
        *(uint4*)(sm + F_QL + sw) = pl[seg];
    }

    float o[8][4];
#pragma unroll
    for (int j = 0; j < 8; j++)
#pragma unroll
        for (int q = 0; q < 4; q++) o[j][q] = 0.0f;
    float m2[2] = {-1e30f, -1e30f};
    float l2[2] = {0.0f, 0.0f};

    const int arow = wid * 16 + (lane & 15);
    const int acol = (lane >> 4) << 3;
    const int brow = ((lane >> 4) << 3) + (lane & 7);
    const int bcol = ((lane >> 3) & 1) << 3;

    for (int kt = 0; kt < NKV; kt += 64) {
        __syncthreads();   // previous chunk's reads complete
        // ---- stage K (64 rows kv x 64 d) and Vt (64 rows d x 64 kv) ----
#pragma unroll
        for (int i = 0; i < 2; i++) {
            int flat = tid + i * 256;        // 0..511
            int row = flat >> 3, seg = flat & 7;
            int sw = SWZ(row * 128 + seg * 16);
            const uint4* kh = (const uint4*)(Kh_g + (size_t)(b * NKV + kt + row) * CQ + hc);
            const uint4* kl = (const uint4*)(Kl_g + (size_t)(b * NKV + kt + row) * CQ + hc);
            *(uint4*)(sm + F_KH + sw) = kh[seg];
            *(uint4*)(sm + F_KL + sw) = kl[seg];
            const uint4* vh = (const uint4*)(Vh_g + (size_t)(b * CQ + hc + row) * NKV + kt);
            const uint4* vl = (const uint4*)(Vl_g + (size_t)(b * CQ + hc + row) * NKV + kt);
            *(uint4*)(sm + F_VH + sw) = vh[seg];
            *(uint4*)(sm + F_VL + sw) = vl[seg];
        }
        __syncthreads();

        // ---- S = Q @ K^T (split: 3 MMAs) ----
        float s[8][4];
#pragma unroll
        for (int j = 0; j < 8; j++)
#pragma unroll
            for (int q = 0; q < 4; q++) s[j][q] = 0.0f;

#pragma unroll
        for (int ks = 0; ks < 4; ks++) {
            uint32_t ah[4], al[4];
            uint32_t aoff = SWZ(arow * 128 + (ks * 16 + acol) * 2);
            ldm_x4(ah, sb + F_QH + aoff);
            ldm_x4(al, sb + F_QL + aoff);
#pragma unroll
            for (int nb = 0; nb < 4; nb++) {
                uint32_t off = SWZ((nb * 16 + brow) * 128 + (ks * 16 + bcol) * 2);
                uint32_t bh[4], bl[4];
                ldm_x4(bh, sb + F_KH + off);
                ldm_x4(bl, sb + F_KL + off);
#pragma unroll
                for (int hh = 0; hh < 2; hh++) {
                    float* cc = s[nb * 2 + hh];
                    mma_bf16(cc, ah, bh[2 * hh], bh[2 * hh + 1]);
                    mma_bf16(cc, ah, bl[2 * hh], bl[2 * hh + 1]);
                    mma_bf16(cc, al, bh[2 * hh], bh[2 * hh + 1]);
                }
            }
        }

        // ---- clamp + online softmax ----
        float mx0 = -1e30f, mx1 = -1e30f;
#pragma unroll
        for (int j = 0; j < 8; j++) {
#pragma unroll
            for (int q = 0; q < 4; q++)
                s[j][q] = fminf(fmaxf(s[j][q], -CLAMP_V), CLAMP_V);
            mx0 = fmaxf(mx0, fmaxf(s[j][0], s[j][1]));
            mx1 = fmaxf(mx1, fmaxf(s[j][2], s[j][3]));
        }
        mx0 = fmaxf(mx0, __shfl_xor_sync(0xffffffffu, mx0, 1));
        mx0 = fmaxf(mx0, __shfl_xor_sync(0xffffffffu, mx0, 2));
        mx1 = fmaxf(mx1, __shfl_xor_sync(0xffffffffu, mx1, 1));
        mx1 = fmaxf(mx1, __shfl_xor_sync(0xffffffffu, mx1, 2));

        float mn0 = fmaxf(m2[0], mx0), mn1 = fmaxf(m2[1], mx1);
        float al0 = __expf(m2[0] - mn0), al1 = __expf(m2[1] - mn1);
        float r0 = 0.0f, r1 = 0.0f;
#pragma unroll
        for (int j = 0; j < 8; j++) {
            s[j][0] = __expf(s[j][0] - mn0);
            s[j][1] = __expf(s[j][1] - mn0);
            s[j][2] = __expf(s[j][2] - mn1);
            s[j][3] = __expf(s[j][3] - mn1);
            r0 += s[j][0] + s[j][1];
            r1 += s[j][2] + s[j][3];
        }
        r0 += __shfl_xor_sync(0xffffffffu, r0, 1);
        r0 += __shfl_xor_sync(0xffffffffu, r0, 2);
        r1 += __shfl_xor_sync(0xffffffffu, r1, 1);
        r1 += __shfl_xor_sync(0xffffffffu, r1, 2);
        l2[0] = l2[0] * al0 + r0;
        l2[1] = l2[1] * al1 + r1;
        m2[0] = mn0; m2[1] = mn1;
#pragma unroll
        for (int j = 0; j < 8; j++) {
            o[j][0] *= al0; o[j][1] *= al0;
            o[j][2] *= al1; o[j][3] *= al1;
        }

        // ---- P fragments from S accumulators, hi/lo split (C->A identity) ----
        uint32_t aph[4][4], apl[4][4];
#pragma unroll
        for (int t = 0; t < 4; t++) {
            psplit2(s[2 * t][0],     s[2 * t][1],     aph[t][0], apl[t][0]);
            psplit2(s[2 * t][2],     s[2 * t][3],     aph[t][1], apl[t][1]);
            psplit2(s[2 * t + 1][0], s[2 * t + 1][1], aph[t][2], apl[t][2]);
            psplit2(s[2 * t + 1][2], s[2 * t + 1][3], aph[t][3], apl[t][3]);
        }

        // ---- O += P @ V  (split: Ph*Vh + Ph*Vl + Pl*Vh) ----
#pragma unroll
        for (int t = 0; t < 4; t++) {
#pragma unroll
            for (int nb = 0; nb < 4; nb++) {
                uint32_t off = SWZ((nb * 16 + brow) * 128 + (t * 16 + bcol) * 2);
                uint32_t bh[4], bl[4];
                ldm_x4(bh, sb + F_VH + off);
                ldm_x4(bl, sb + F_VL + off);
#pragma unroll
                for (int hh = 0; hh < 2; hh++) {
                    float* cc = o[nb * 2 + hh];
                    mma_bf16(cc, aph[t], bh[2 * hh], bh[2 * hh + 1]);
                    mma_bf16(cc, aph[t], bl[2 * hh], bl[2 * hh + 1]);
                    mma_bf16(cc, apl[t], bh[2 * hh], bh[2 * hh + 1]);
                }
            }
        }
    }

    // ---- epilogue: normalize, split, store bf16x2 ----
    const float il0 = 1.0f / l2[0], il1 = 1.0f / l2[1];
    const int row = qrow0 + wid * 16 + (lane >> 2);
#pragma unroll
    for (int j = 0; j < 8; j++) {
        const int col = hc + j * 8 + (lane & 3) * 2;
        uint32_t h0, l0, h1, l1, h2, l2r, h3, l3;
        bsplit(o[j][0] * il0, h0, l0);
        bsplit(o[j][1] * il0, h1, l1);
        bsplit(o[j][2] * il1, h2, l2r);
        bsplit(o[j][3] * il1, h3, l3);
        *(uint32_t*)&Xh_g[(size_t)row * CQ + col]       = h0 | (h1 << 16);
        *(uint32_t*)&Xl_g[(size_t)row * CQ + col]       = l0 | (l1 << 16);
        *(uint32_t*)&Xh_g[(size_t)(row + 8) * CQ + col] = h2 | (h3 << 16);
        *(uint32_t*)&Xl_g[(size_t)(row + 8) * CQ + col] = l2r | (l3 << 16);
    }
}

// ---------------------------------------------------------------------------
// launch
// ---------------------------------------------------------------------------
extern "C" void kernel_launch(void* const* d_in, const int* in_sizes, int n_in,
                              void* d_out, int out_size)
{
    const float* query = (const float*)d_in[0];
    const float* kv    = (const float*)d_in[1];
    const float* Wq    = (const float*)d_in[2];
    const float* bq    = (const float*)d_in[3];
    const float* Wk    = (const float*)d_in[4];
    const float* bk    = (const float*)d_in[5];
    const float* Wv    = (const float*)d_in[6];
    const float* bv    = (const float*)d_in[7];
    const float* Wo    = (const float*)d_in[8];
    const float* bo    = (const float*)d_in[9];
    float* out = (float*)d_out;

    __nv_bfloat16 *qh, *ql, *kh, *kl, *vth, *vtl, *xh, *xl;
    cudaGetSymbolAddress((void**)&qh,  g_qh);  cudaGetSymbolAddress((void**)&ql,  g_ql);
    cudaGetSymbolAddress((void**)&kh,  g_kh);  cudaGetSymbolAddress((void**)&kl,  g_kl);
    cudaGetSymbolAddress((void**)&vth, g_vth); cudaGetSymbolAddress((void**)&vtl, g_vtl);
    cudaGetSymbolAddress((void**)&xh,  g_xh);  cudaGetSymbolAddress((void**)&xl,  g_xl);

    __nv_bfloat16 *wqh, *wql, *wkh, *wkl, *wvh, *wvl, *woh, *wol;
    cudaGetSymbolAddress((void**)&wqh, g_wqh); cudaGetSymbolAddress((void**)&wql, g_wql);
    cudaGetSymbolAddress((void**)&wkh, g_wkh); cudaGetSymbolAddress((void**)&wkl, g_wkl);
    cudaGetSymbolAddress((void**)&wvh, g_wvh); cudaGetSymbolAddress((void**)&wvl, g_wvl);
    cudaGetSymbolAddress((void**)&woh, g_woh); cudaGetSymbolAddress((void**)&wol, g_wol);

    dim3 tb(32, 8);
    wsplit_t<<<dim3(CQ / 32, CQ / 32),  tb>>>(Wq, wqh, wql, CQ,  CQ);
    wsplit_t<<<dim3(CQ / 32, CKV / 32), tb>>>(Wk, wkh, wkl, CKV, CQ);
    wsplit_t<<<dim3(CQ / 32, CKV / 32), tb>>>(Wv, wvh, wvl, CKV, CQ);
    wsplit_t<<<dim3(CQ / 32, CQ / 32),  tb>>>(Wo, woh, wol, CQ,  CQ);

    const int M = B_ * NQ;   // 8192
    cudaFuncSetAttribute(gemm_tc<0, 1>, cudaFuncAttributeMaxDynamicSharedMemorySize, SMEM_GEMM);
    cudaFuncSetAttribute(gemm_tc<0, 2>, cudaFuncAttributeMaxDynamicSharedMemorySize, SMEM_GEMM);
    cudaFuncSetAttribute(gemm_tc<1, 0>, cudaFuncAttributeMaxDynamicSharedMemorySize, SMEM_GEMM);
    cudaFuncSetAttribute(flash_mma, cudaFuncAttributeMaxDynamicSharedMemorySize, SMEM_FLASH);

    dim3 gg(CQ / 128, M / 128);   // (8, 64)

    // Q proj -> bf16 hi/lo, scale folded
    gemm_tc<0, 1><<<gg, 256, SMEM_GEMM>>>(query, nullptr, nullptr, wqh, wql, bq,
                                          nullptr, qh, ql, M, CQ, CQ, SCALE);
    // K proj -> bf16 hi/lo
    gemm_tc<0, 1><<<gg, 256, SMEM_GEMM>>>(kv, nullptr, nullptr, wkh, wkl, bk,
                                          nullptr, kh, kl, M, CKV, CQ, 1.0f);
    // V proj -> bf16 hi/lo transposed per head
    gemm_tc<0, 2><<<gg, 256, SMEM_GEMM>>>(kv, nullptr, nullptr, wvh, wvl, bv,
                                          nullptr, vth, vtl, M, CKV, CQ, 1.0f);
    // attention
    flash_mma<<<dim3(NQ / 128, NH, B_), 256, SMEM_FLASH>>>(qh, ql, kh, kl,
                                                           vth, vtl, xh, xl);
    // output proj (pre-split A) -> fp32 out
    gemm_tc<1, 0><<<gg, 256, SMEM_GEMM>>>(nullptr, xh, xl, woh, wol, bo,
                                          out, nullptr, nullptr, M, CQ, CQ, 1.0f);
}

// round 6
// speedup vs baseline: 2.9858x; 1.9639x over previous
#include <cuda_runtime.h>
#include <cuda_bf16.h>
#include <cstdint>

// Problem constants
#define B_    4
#define NQ    2048
#define NKV   2048
#define CQ    1024
#define CKV   768
#define NH    16
#define HD    64
#define SCALE 0.125f        // HD^-0.5
#define CLAMP_V 1.0e4f

// Scratch (allocation-free: __device__ globals). All bf16 hi/lo pairs.
__device__ __nv_bfloat16 g_qsh[B_ * NQ * CQ],  g_qsl[B_ * NQ * CQ];   // split query input
__device__ __nv_bfloat16 g_kvh[B_ * NKV * CKV], g_kvl[B_ * NKV * CKV]; // split kv input
__device__ __nv_bfloat16 g_qh[B_ * NQ * CQ],  g_ql[B_ * NQ * CQ];
__device__ __nv_bfloat16 g_kh[B_ * NKV * CQ], g_kl[B_ * NKV * CQ];
__device__ __nv_bfloat16 g_vh[B_ * NKV * CQ], g_vl[B_ * NKV * CQ];
__device__ __nv_bfloat16 g_xh[B_ * NQ * CQ],  g_xl[B_ * NQ * CQ];

// Pre-transposed + hi/lo-split weights, [N][K] K-major bf16
__device__ __nv_bfloat16 g_wqh[CQ * CQ],  g_wql[CQ * CQ];
__device__ __nv_bfloat16 g_wkh[CQ * CKV], g_wkl[CQ * CKV];
__device__ __nv_bfloat16 g_wvh[CQ * CKV], g_wvl[CQ * CKV];
__device__ __nv_bfloat16 g_woh[CQ * CQ],  g_wol[CQ * CQ];

// ---------------------------------------------------------------------------
// helpers
// ---------------------------------------------------------------------------
__device__ __forceinline__ uint32_t smem_u32(const void* p) {
    uint32_t a;
    asm("{ .reg .u64 t; cvta.to.shared.u64 t, %1; cvt.u32.u64 %0, t; }"
        : "=r"(a) : "l"(p));
    return a;
}
__device__ __forceinline__ void ldm_x4(uint32_t* r, uint32_t addr) {
    asm volatile("ldmatrix.sync.aligned.m8n8.x4.shared.b16 {%0,%1,%2,%3}, [%4];"
        : "=r"(r[0]), "=r"(r[1]), "=r"(r[2]), "=r"(r[3]) : "r"(addr));
}
__device__ __forceinline__ void ldm_x4_t(uint32_t* r, uint32_t addr) {
    asm volatile("ldmatrix.sync.aligned.m8n8.x4.trans.shared.b16 {%0,%1,%2,%3}, [%4];"
        : "=r"(r[0]), "=r"(r[1]), "=r"(r[2]), "=r"(r[3]) : "r"(addr));
}
__device__ __forceinline__ void mma_bf16(float* c, const uint32_t* a,
                                         uint32_t b0, uint32_t b1) {
    asm volatile(
        "mma.sync.aligned.m16n8k16.row.col.f32.bf16.bf16.f32 "
        "{%0,%1,%2,%3}, {%4,%5,%6,%7}, {%8,%9}, {%0,%1,%2,%3};"
        : "+f"(c[0]), "+f"(c[1]), "+f"(c[2]), "+f"(c[3])
        : "r"(a[0]), "r"(a[1]), "r"(a[2]), "r"(a[3]), "r"(b0), "r"(b1));
}
#define CP16(dst, src) \
    asm volatile("cp.async.cg.shared.global [%0], [%1], 16;" \
        :: "r"(dst), "l"(src))
#define CP_COMMIT() asm volatile("cp.async.commit_group;" ::: "memory")
#define CP_WAIT1()  asm volatile("cp.async.wait_group 1;" ::: "memory")
#define CP_WAIT0()  asm volatile("cp.async.wait_group 0;" ::: "memory")

#define SWZ(o) ((o) ^ (((o) >> 3) & 0x70))

__device__ __forceinline__ void bsplit(float x, uint32_t& hi, uint32_t& lo) {
    __nv_bfloat16 h = __float2bfloat16(x);
    float r = x - __bfloat162float(h);
    __nv_bfloat16 l = __float2bfloat16(r);
    hi = (uint32_t)__bfloat16_as_ushort(h);
    lo = (uint32_t)__bfloat16_as_ushort(l);
}
__device__ __forceinline__ void psplit2(float a, float b,
                                        uint32_t& hp, uint32_t& lp) {
    uint32_t ha, la, hb, lb;
    bsplit(a, ha, la);
    bsplit(b, hb, lb);
    hp = ha | (hb << 16);
    lp = la | (lb << 16);
}

// ---------------------------------------------------------------------------
// Input pre-pass: fp32 -> bf16 hi/lo elementwise. n % 1024 == 0.
// ---------------------------------------------------------------------------
__global__ void insplit(const float* __restrict__ in,
                        __nv_bfloat16* __restrict__ hi,
                        __nv_bfloat16* __restrict__ lo)
{
    int idx = blockIdx.x * 256 + threadIdx.x;
    float4 a = ((const float4*)in)[idx];
    uint32_t h0, l0, h1, l1, h2, l2, h3, l3;
    bsplit(a.x, h0, l0); bsplit(a.y, h1, l1);
    bsplit(a.z, h2, l2); bsplit(a.w, h3, l3);
    uint2 hv = make_uint2(h0 | (h1 << 16), h2 | (h3 << 16));
    uint2 lv = make_uint2(l0 | (l1 << 16), l2 | (l3 << 16));
    ((uint2*)hi)[idx] = hv;
    ((uint2*)lo)[idx] = lv;
}

// ---------------------------------------------------------------------------
// Weight pre-pass: W[K,N] fp32 -> Thi/Tlo[N,K] bf16 (transposed + split)
// ---------------------------------------------------------------------------
__global__ void wsplit_t(const float* __restrict__ W,
                         __nv_bfloat16* __restrict__ Thi,
                         __nv_bfloat16* __restrict__ Tlo, int K, int N)
{
    __shared__ float t[32][33];
    const int n0 = blockIdx.x * 32, k0 = blockIdx.y * 32;
    const int tx = threadIdx.x, ty = threadIdx.y;
#pragma unroll
    for (int e = 0; e < 4; e++)
        t[ty + 8 * e][tx] = W[(size_t)(k0 + ty + 8 * e) * N + n0 + tx];
    __syncthreads();
#pragma unroll
    for (int e = 0; e < 4; e++) {
        float x = t[tx][ty + 8 * e];
        __nv_bfloat16 h = __float2bfloat16(x);
        __nv_bfloat16 l = __float2bfloat16(x - __bfloat162float(h));
        size_t o = (size_t)(n0 + ty + 8 * e) * K + k0 + tx;
        Thi[o] = h;
        Tlo[o] = l;
    }
}

// ---------------------------------------------------------------------------
// mma.sync split-bf16 GEMM, cp.async double-buffered.
// A pre-split bf16 hi/lo [M,K]; B pre-split [N,K].
// OMODE 0: fp32 C + bias.  OMODE 1: bf16 hi/lo C, (acc+bias)*oscale.
// CTA 128x128, K-chunk 64, 256 threads (8 warps = 4m x 2n).
// ---------------------------------------------------------------------------
#define G_BIAS 0
#define G_STAGE(s) (1024 + (s) * 65536)   // per stage: AHI|ALO|BHI|BLO 16KB each
#define SMEM_GEMM (1024 + 2 * 65536)      // 132096 B

template<int OMODE>
__global__ __launch_bounds__(256)
void gemm_tc(const __nv_bfloat16* __restrict__ Ah,
             const __nv_bfloat16* __restrict__ Al,
             const __nv_bfloat16* __restrict__ Bhi,
             const __nv_bfloat16* __restrict__ Blo,
             const float* __restrict__ bias,
             float* __restrict__ Cf,
             __nv_bfloat16* __restrict__ Chi,
             __nv_bfloat16* __restrict__ Clo,
             int M, int K, int N, float oscale)
{
    extern __shared__ char sm[];
    const uint32_t sb = smem_u32(sm);
    const int tid  = threadIdx.x;
    const int wid  = tid >> 5, lane = tid & 31;
    const int n0   = blockIdx.x * 128, m0 = blockIdx.y * 128;
    const int wm   = wid & 3;
    const int wn   = wid >> 2;

    if (tid < 128) ((float*)(sm + G_BIAS))[tid] = bias[n0 + tid];

    float acc[2][8][4];
#pragma unroll
    for (int i = 0; i < 2; i++)
#pragma unroll
        for (int j = 0; j < 8; j++)
#pragma unroll
            for (int q = 0; q < 4; q++) acc[i][j][q] = 0.0f;

    const int arow = wm * 32 + (lane & 15);
    const int acol = (lane >> 4) << 3;
    const int brow = wn * 64 + ((lane >> 4) << 3) + (lane & 7);
    const int bcol = ((lane >> 3) & 1) << 3;

    const int nchunks = K >> 6;

    // staging: 16 cp.async x 16B per thread per stage (4 arrays x 1024 segs)
    auto stage = [&](int c) {
        const int k0 = c << 6;
        const uint32_t base = sb + G_STAGE(c & 1);
#pragma unroll
        for (int i = 0; i < 16; i++) {
            int flat = tid + i * 256;             // 0..4095
            int arr  = flat >> 10;                // 0..3
            int r    = (flat >> 3) & 127;
            int sg   = flat & 7;
            uint32_t dst = base + arr * 16384 + SWZ(r * 128 + sg * 16);
            const __nv_bfloat16* src;
            if      (arr == 0) src = Ah  + (size_t)(m0 + r) * K + k0 + sg * 8;
            else if (arr == 1) src = Al  + (size_t)(m0 + r) * K + k0 + sg * 8;
            else if (arr == 2) src = Bhi + (size_t)(n0 + r) * K + k0 + sg * 8;
            else               src = Blo + (size_t)(n0 + r) * K + k0 + sg * 8;
            CP16(dst, src);
        }
    };

    stage(0); CP_COMMIT();

    for (int c = 0; c < nchunks; c++) {
        if (c + 1 < nchunks) { stage(c + 1); CP_COMMIT(); CP_WAIT1(); }
        else                 { CP_WAIT0(); }
        __syncthreads();

        const uint32_t bufa = sb + G_STAGE(c & 1);
        const uint32_t bufb = bufa + 32768;
#pragma unroll
        for (int ks = 0; ks < 4; ks++) {
            uint32_t ah[2][4], al[2][4];
#pragma unroll
            for (int mi = 0; mi < 2; mi++) {
                uint32_t off = SWZ((arow + mi * 16) * 128 + (ks * 16 + acol) * 2);
                ldm_x4(ah[mi], bufa + off);
                ldm_x4(al[mi], bufa + 16384 + off);
            }
#pragma unroll
            for (int nb = 0; nb < 4; nb++) {
                uint32_t off = SWZ((brow + nb * 16) * 128 + (ks * 16 + bcol) * 2);
                uint32_t bh[4], bl[4];
                ldm_x4(bh, bufb + off);
                ldm_x4(bl, bufb + 16384 + off);
#pragma unroll
                for (int h = 0; h < 2; h++)
#pragma unroll
                    for (int mi = 0; mi < 2; mi++) {
                        float* cc = acc[mi][nb * 2 + h];
                        mma_bf16(cc, ah[mi], bh[2 * h], bh[2 * h + 1]);
                        mma_bf16(cc, ah[mi], bl[2 * h], bl[2 * h + 1]);
                        mma_bf16(cc, al[mi], bh[2 * h], bh[2 * h + 1]);
                    }
            }
        }
        __syncthreads();
    }

    const float* bsm = (const float*)(sm + G_BIAS);
    const int qr = lane >> 2;
    const int qc = (lane & 3) * 2;
#pragma unroll
    for (int mi = 0; mi < 2; mi++) {
        const int r0 = m0 + wm * 32 + mi * 16 + qr;
#pragma unroll
        for (int j = 0; j < 8; j++) {
            const int cb = wn * 64 + j * 8 + qc;
            const int col = n0 + cb;
            float v0 = acc[mi][j][0] + bsm[cb];
            float v1 = acc[mi][j][1] + bsm[cb + 1];
            float v2 = acc[mi][j][2] + bsm[cb];
            float v3 = acc[mi][j][3] + bsm[cb + 1];
            if (OMODE == 0) {
                *(float2*)&Cf[(size_t)r0 * N + col]       = make_float2(v0, v1);
                *(float2*)&Cf[(size_t)(r0 + 8) * N + col] = make_float2(v2, v3);
            } else {
                v0 *= oscale; v1 *= oscale; v2 *= oscale; v3 *= oscale;
                uint32_t h0, l0, h1, l1, h2, l2, h3, l3;
                bsplit(v0, h0, l0); bsplit(v1, h1, l1);
                bsplit(v2, h2, l2); bsplit(v3, h3, l3);
                *(uint32_t*)&Chi[(size_t)r0 * N + col]       = h0 | (h1 << 16);
                *(uint32_t*)&Clo[(size_t)r0 * N + col]       = l0 | (l1 << 16);
                *(uint32_t*)&Chi[(size_t)(r0 + 8) * N + col] = h2 | (h3 << 16);
                *(uint32_t*)&Clo[(size_t)(r0 + 8) * N + col] = l2 | (l3 << 16);
            }
        }
    }
}

// ---------------------------------------------------------------------------
// flash attention with mma.sync + cp.async double-buffered K/V.
// BM=128 q rows, BN=64 kv chunk, D=64. grid (NQ/128, NH, B_), 256 threads.
// Q/K/V pre-split [B*N, CQ] row-major; V's B-fragments via ldmatrix.trans.
// Output X as bf16 hi/lo [B*NQ, CQ]. P hi/lo split for P@V.
// ---------------------------------------------------------------------------
#define F_QH 0
#define F_QL 16384
#define F_STAGE(s) (32768 + (s) * 32768)  // per stage: KH|KL|VH|VL 8KB each
#define SMEM_FLASH (32768 + 2 * 32768)    // 98304 B

__global__ __launch_bounds__(256)
void flash_mma(const __nv_bfloat16* __restrict__ Qh_g,
               const __nv_bfloat16* __restrict__ Ql_g,
               const __nv_bfloat16* __restrict__ Kh_g,
               const __nv_bfloat16* __restrict__ Kl_g,
               const __nv_bfloat16* __restrict__ Vh_g,
               const __nv_bfloat16* __restrict__ Vl_g,
               __nv_bfloat16* __restrict__ Xh_g,
               __nv_bfloat16* __restrict__ Xl_g)
{
    extern __shared__ char sm[];
    const uint32_t sb = smem_u32(sm);
    const int tid  = threadIdx.x;
    const int wid  = tid >> 5, lane = tid & 31;
    const int h    = blockIdx.y, b = blockIdx.z;
    const int hc   = h * HD;
    const int qrow0 = b * NQ + blockIdx.x * 128;

    // ---- stage Q (128 rows x 64 bf16, hi+lo) ----
#pragma unroll
    for (int i = 0; i < 4; i++) {
        int flat = tid + i * 256;            // 0..1023
        int row = flat >> 3, seg = flat & 7;
        const uint4* ph = (const uint4*)(Qh_g + (size_t)(qrow0 + row) * CQ + hc);
        const uint4* pl = (const uint4*)(Ql_g + (size_t)(qrow0 + row) * CQ + hc);
        int sw = SWZ(row * 128 + seg * 16);
        *(uint4*)(sm + F_QH + sw) = ph[seg];
        *(uint4*)(sm + F_QL + sw) = pl[seg];
    }

    float o[8][4];
#pragma unroll
    for (int j = 0; j < 8; j++)
#pragma unroll
        for (int q = 0; q < 4; q++) o[j][q] = 0.0f;
    float m2[2] = {-1e30f, -1e30f};
    float l2[2] = {0.0f, 0.0f};

    const int arow = wid * 16 + (lane & 15);
    const int acol = (lane >> 4) << 3;
    const int brow = ((lane >> 4) << 3) + (lane & 7);
    const int bcol = ((lane >> 3) & 1) << 3;
    const int vrow = lane & 7, vm = lane >> 3;   // trans-ldmatrix addressing

    const int NCH = NKV / 64;  // 32

    // stage chunk: 8 cp.async x 16B per thread (4 arrays x 512 segs)
    auto stage = [&](int c) {
        const int kt = c << 6;
        const uint32_t base = sb + F_STAGE(c & 1);
#pragma unroll
        for (int i = 0; i < 8; i++) {
            int flat = tid + i * 256;             // 0..2047
            int arr  = flat >> 9;                 // 0..3
            int r    = (flat >> 3) & 63;
            int sg   = flat & 7;
            uint32_t dst = base + arr * 8192 + SWZ(r * 128 + sg * 16);
            size_t g = (size_t)(b * NKV + kt + r) * CQ + hc + sg * 8;
            const __nv_bfloat16* src;
            if      (arr == 0) src = Kh_g + g;
            else if (arr == 1) src = Kl_g + g;
            else if (arr == 2) src = Vh_g + g;
            else               src = Vl_g + g;
            CP16(dst, src);
        }
    };

    stage(0); CP_COMMIT();

    for (int c = 0; c < NCH; c++) {
        if (c + 1 < NCH) { stage(c + 1); CP_COMMIT(); CP_WAIT1(); }
        else             { CP_WAIT0(); }
        __syncthreads();

        const uint32_t kbase = sb + F_STAGE(c & 1);
        const uint32_t vbase = kbase + 16384;

        // ---- S = Q @ K^T (split: 3 MMAs) ----
        float s[8][4];
#pragma unroll
        for (int j = 0; j < 8; j++)
#pragma unroll
            for (int q = 0; q < 4; q++) s[j][q] = 0.0f;

#pragma unroll
        for (int ks = 0; ks < 4; ks++) {
            uint32_t ah[4], al[4];
            uint32_t aoff = SWZ(arow * 128 + (ks * 16 + acol) * 2);
            ldm_x4(ah, sb + F_QH + aoff);
            ldm_x4(al, sb + F_QL + aoff);
#pragma unroll
            for (int nb = 0; nb < 4; nb++) {
                uint32_t off = SWZ((nb * 16 + brow) * 128 + (ks * 16 + bcol) * 2);
                uint32_t bh[4], bl[4];
                ldm_x4(bh, kbase + off);
                ldm_x4(bl, kbase + 8192 + off);
#pragma unroll
                for (int hh = 0; hh < 2; hh++) {
                    float* cc = s[nb * 2 + hh];
                    mma_bf16(cc, ah, bh[2 * hh], bh[2 * hh + 1]);
                    mma_bf16(cc, ah, bl[2 * hh], bl[2 * hh + 1]);
                    mma_bf16(cc, al, bh[2 * hh], bh[2 * hh + 1]);
                }
            }
        }

        // ---- clamp + online softmax ----
        float mx0 = -1e30f, mx1 = -1e30f;
#pragma unroll
        for (int j = 0; j < 8; j++) {
#pragma unroll
            for (int q = 0; q < 4; q++)
                s[j][q] = fminf(fmaxf(s[j][q], -CLAMP_V), CLAMP_V);
            mx0 = fmaxf(mx0, fmaxf(s[j][0], s[j][1]));
            mx1 = fmaxf(mx1, fmaxf(s[j][2], s[j][3]));
        }
        mx0 = fmaxf(mx0, __shfl_xor_sync(0xffffffffu, mx0, 1));
        mx0 = fmaxf(mx0, __shfl_xor_sync(0xffffffffu, mx0, 2));
        mx1 = fmaxf(mx1, __shfl_xor_sync(0xffffffffu, mx1, 1));
        mx1 = fmaxf(mx1, __shfl_xor_sync(0xffffffffu, mx1, 2));

        float mn0 = fmaxf(m2[0], mx0), mn1 = fmaxf(m2[1], mx1);
        float al0 = __expf(m2[0] - mn0), al1 = __expf(m2[1] - mn1);
        float r0 = 0.0f, r1 = 0.0f;
#pragma unroll
        for (int j = 0; j < 8; j++) {
            s[j][0] = __expf(s[j][0] - mn0);
            s[j][1] = __expf(s[j][1] - mn0);
            s[j][2] = __expf(s[j][2] - mn1);
            s[j][3] = __expf(s[j][3] - mn1);
            r0 += s[j][0] + s[j][1];
            r1 += s[j][2] + s[j][3];
        }
        r0 += __shfl_xor_sync(0xffffffffu, r0, 1);
        r0 += __shfl_xor_sync(0xffffffffu, r0, 2);
        r1 += __shfl_xor_sync(0xffffffffu, r1, 1);
        r1 += __shfl_xor_sync(0xffffffffu, r1, 2);
        l2[0] = l2[0] * al0 + r0;
        l2[1] = l2[1] * al1 + r1;
        m2[0] = mn0; m2[1] = mn1;
#pragma unroll
        for (int j = 0; j < 8; j++) {
            o[j][0] *= al0; o[j][1] *= al0;
            o[j][2] *= al1; o[j][3] *= al1;
        }

        // ---- P fragments from S accumulators, hi/lo split ----
        uint32_t aph[4][4], apl[4][4];
#pragma unroll
        for (int t = 0; t < 4; t++) {
            psplit2(s[2 * t][0],     s[2 * t][1],     aph[t][0], apl[t][0]);
            psplit2(s[2 * t][2],     s[2 * t][3],     aph[t][1], apl[t][1]);
            psplit2(s[2 * t + 1][0], s[2 * t + 1][1], aph[t][2], apl[t][2]);
            psplit2(s[2 * t + 1][2], s[2 * t + 1][3], aph[t][3], apl[t][3]);
        }

        // ---- O += P @ V  via trans-ldmatrix on row-major V[kv][d] ----
#pragma unroll
        for (int t = 0; t < 4; t++) {
#pragma unroll
            for (int nb = 0; nb < 4; nb++) {
                int kv = t * 16 + (vm & 1) * 8 + vrow;
                int d  = nb * 16 + (vm >> 1) * 8;
                uint32_t off = SWZ(kv * 128 + d * 2);
                uint32_t bh[4], bl[4];
                ldm_x4_t(bh, vbase + off);
                ldm_x4_t(bl, vbase + 8192 + off);
#pragma unroll
                for (int hh = 0; hh < 2; hh++) {
                    float* cc = o[nb * 2 + hh];
                    mma_bf16(cc, aph[t], bh[2 * hh], bh[2 * hh + 1]);
                    mma_bf16(cc, aph[t], bl[2 * hh], bl[2 * hh + 1]);
                    mma_bf16(cc, apl[t], bh[2 * hh], bh[2 * hh + 1]);
                }
            }
        }
        __syncthreads();
    }

    // ---- epilogue: normalize, split, store bf16x2 ----
    const float il0 = 1.0f / l2[0], il1 = 1.0f / l2[1];
    const int row = qrow0 + wid * 16 + (lane >> 2);
#pragma unroll
    for (int j = 0; j < 8; j++) {
        const int col = hc + j * 8 + (lane & 3) * 2;
        uint32_t h0, l0, h1, l1, h2, l2r, h3, l3;
        bsplit(o[j][0] * il0, h0, l0);
        bsplit(o[j][1] * il0, h1, l1);
        bsplit(o[j][2] * il1, h2, l2r);
        bsplit(o[j][3] * il1, h3, l3);
        *(uint32_t*)&Xh_g[(size_t)row * CQ + col]       = h0 | (h1 << 16);
        *(uint32_t*)&Xl_g[(size_t)row * CQ + col]       = l0 | (l1 << 16);
        *(uint32_t*)&Xh_g[(size_t)(row + 8) * CQ + col] = h2 | (h3 << 16);
        *(uint32_t*)&Xl_g[(size_t)(row + 8) * CQ + col] = l2r | (l3 << 16);
    }
}

// ---------------------------------------------------------------------------
// launch
// ---------------------------------------------------------------------------
extern "C" void kernel_launch(void* const* d_in, const int* in_sizes, int n_in,
                              void* d_out, int out_size)
{
    const float* query = (const float*)d_in[0];
    const float* kv    = (const float*)d_in[1];
    const float* Wq    = (const float*)d_in[2];
    const float* bq    = (const float*)d_in[3];
    const float* Wk    = (const float*)d_in[4];
    const float* bk    = (const float*)d_in[5];
    const float* Wv    = (const float*)d_in[6];
    const float* bv    = (const float*)d_in[7];
    const float* Wo    = (const float*)d_in[8];
    const float* bo    = (const float*)d_in[9];
    float* out = (float*)d_out;

    __nv_bfloat16 *qsh, *qsl, *kvh, *kvl;
    __nv_bfloat16 *qh, *ql, *kh, *kl, *vh, *vl, *xh, *xl;
    cudaGetSymbolAddress((void**)&qsh, g_qsh); cudaGetSymbolAddress((void**)&qsl, g_qsl);
    cudaGetSymbolAddress((void**)&kvh, g_kvh); cudaGetSymbolAddress((void**)&kvl, g_kvl);
    cudaGetSymbolAddress((void**)&qh,  g_qh);  cudaGetSymbolAddress((void**)&ql,  g_ql);
    cudaGetSymbolAddress((void**)&kh,  g_kh);  cudaGetSymbolAddress((void**)&kl,  g_kl);
    cudaGetSymbolAddress((void**)&vh,  g_vh);  cudaGetSymbolAddress((void**)&vl,  g_vl);
    cudaGetSymbolAddress((void**)&xh,  g_xh);  cudaGetSymbolAddress((void**)&xl,  g_xl);

    __nv_bfloat16 *wqh, *wql, *wkh, *wkl, *wvh, *wvl, *woh, *wol;
    cudaGetSymbolAddress((void**)&wqh, g_wqh); cudaGetSymbolAddress((void**)&wql, g_wql);
    cudaGetSymbolAddress((void**)&wkh, g_wkh); cudaGetSymbolAddress((void**)&wkl, g_wkl);
    cudaGetSymbolAddress((void**)&wvh, g_wvh); cudaGetSymbolAddress((void**)&wvl, g_wvl);
    cudaGetSymbolAddress((void**)&woh, g_woh); cudaGetSymbolAddress((void**)&wol, g_wol);

    // pre-split inputs and weights
    insplit<<<(B_ * NQ * CQ) / 1024, 256>>>(query, qsh, qsl);
    insplit<<<(B_ * NKV * CKV) / 1024, 256>>>(kv, kvh, kvl);
    dim3 tb(32, 8);
    wsplit_t<<<dim3(CQ / 32, CQ / 32),  tb>>>(Wq, wqh, wql, CQ,  CQ);
    wsplit_t<<<dim3(CQ / 32, CKV / 32), tb>>>(Wk, wkh, wkl, CKV, CQ);
    wsplit_t<<<dim3(CQ / 32, CKV / 32), tb>>>(Wv, wvh, wvl, CKV, CQ);
    wsplit_t<<<dim3(CQ / 32, CQ / 32),  tb>>>(Wo, woh, wol, CQ,  CQ);

    const int M = B_ * NQ;   // 8192
    cudaFuncSetAttribute(gemm_tc<0>, cudaFuncAttributeMaxDynamicSharedMemorySize, SMEM_GEMM);
    cudaFuncSetAttribute(gemm_tc<1>, cudaFuncAttributeMaxDynamicSharedMemorySize, SMEM_GEMM);
    cudaFuncSetAttribute(flash_mma, cudaFuncAttributeMaxDynamicSharedMemorySize, SMEM_FLASH);

    dim3 gg(CQ / 128, M / 128);   // (8, 64)

    // Q proj -> bf16 hi/lo, scale folded into output
    gemm_tc<1><<<gg, 256, SMEM_GEMM>>>(qsh, qsl, wqh, wql, bq,
                                       nullptr, qh, ql, M, CQ, CQ, SCALE);
    // K proj -> bf16 hi/lo
    gemm_tc<1><<<gg, 256, SMEM_GEMM>>>(kvh, kvl, wkh, wkl, bk,
                                       nullptr, kh, kl, M, CKV, CQ, 1.0f);
    // V proj -> bf16 hi/lo (row-major, same as K)
    gemm_tc<1><<<gg, 256, SMEM_GEMM>>>(kvh, kvl, wvh, wvl, bv,
                                       nullptr, vh, vl, M, CKV, CQ, 1.0f);
    // attention
    flash_mma<<<dim3(NQ / 128, NH, B_), 256, SMEM_FLASH>>>(qh, ql, kh, kl,
                                                           vh, vl, xh, xl);
    // output proj -> fp32 out
    gemm_tc<0><<<gg, 256, SMEM_GEMM>>>(xh, xl, woh, wol, bo,
                                       out, nullptr, nullptr, M, CQ, CQ, 1.0f);
}